// round 16
// baseline (speedup 1.0000x reference)
#include <cuda_runtime.h>
#include <cuda_bf16.h>
#include <math.h>
#include <stdint.h>

#define BATCH   64
#define CH      96
#define HW      12544
#define MTOK    6
#define HEADS   4
#define RQ      24
#define DMODEL  192
#define QDIM    384
// SCALE * log2(e): scores feed ex2 directly
#define SCALE_F (0.10206207261596575f * 1.4426950408889634f)
#define SPLITS  14
#define CHUNK   896
#define TILE    128
#define TILES_PER 7
#define KQ      8           // qproj split-k
#define XSTR    136         // bf16 per X row (128+8)
#define FSTR    132         // fp32 per staging row (128+4)
#define QSTR    104         // bf16 per Q row (96+8)
#define PSTR    136         // bf16 per P row (128+8), rows = q

#define OFF_XF   0          // 96*132*4 = 50688
#define OFF_Q    50688      // 24*104*2 = 4992
#define OFF_X    55680      // 96*136*2 = 26112
#define OFF_P    81792      // 24*136*2 = 6528
#define OFF_LR   88320      // 8*32*4   = 1024
#define SMEM_TOT 89344

__device__ float g_Qp[KQ * BATCH * RQ * CH];
__device__ float g_Lx[BATCH * SPLITS * RQ];
__device__ float g_Ox[BATCH * SPLITS * RQ * CH];

// ---------------------------------------------------------------------------
__device__ __forceinline__ uint32_t smem_u32(const void* p) {
    return (uint32_t)__cvta_generic_to_shared(p);
}
__device__ __forceinline__ void ldm_x4(uint32_t& r0, uint32_t& r1, uint32_t& r2,
                                       uint32_t& r3, uint32_t addr) {
    asm volatile("ldmatrix.sync.aligned.m8n8.x4.shared.b16 {%0,%1,%2,%3}, [%4];"
                 : "=r"(r0), "=r"(r1), "=r"(r2), "=r"(r3) : "r"(addr));
}
__device__ __forceinline__ void ldm_x4_t(uint32_t& r0, uint32_t& r1, uint32_t& r2,
                                         uint32_t& r3, uint32_t addr) {
    asm volatile("ldmatrix.sync.aligned.m8n8.x4.trans.shared.b16 {%0,%1,%2,%3}, [%4];"
                 : "=r"(r0), "=r"(r1), "=r"(r2), "=r"(r3) : "r"(addr));
}
__device__ __forceinline__ void ldm_x2(uint32_t& r0, uint32_t& r1, uint32_t addr) {
    asm volatile("ldmatrix.sync.aligned.m8n8.x2.shared.b16 {%0,%1}, [%2];"
                 : "=r"(r0), "=r"(r1) : "r"(addr));
}
__device__ __forceinline__ void mma16816(float* c, const uint32_t* a,
                                         uint32_t b0, uint32_t b1) {
    asm volatile("mma.sync.aligned.m16n8k16.row.col.f32.bf16.bf16.f32 "
                 "{%0,%1,%2,%3}, {%4,%5,%6,%7}, {%8,%9}, {%0,%1,%2,%3};"
                 : "+f"(c[0]), "+f"(c[1]), "+f"(c[2]), "+f"(c[3])
                 : "r"(a[0]), "r"(a[1]), "r"(a[2]), "r"(a[3]), "r"(b0), "r"(b1));
}
__device__ __forceinline__ void cpasync16(uint32_t dst, const void* src) {
    asm volatile("cp.async.cg.shared.global [%0], [%1], 16;" :: "r"(dst), "l"(src));
}
#define CP_COMMIT() asm volatile("cp.async.commit_group;" ::: "memory")
#define CP_WAIT0()  asm volatile("cp.async.wait_group 0;" ::: "memory")

__device__ __forceinline__ uint32_t pack_bf16(float a, float b) {
    __nv_bfloat162 h2 = __floats2bfloat162_rn(a, b);
    return *(uint32_t*)&h2;
}
__device__ __forceinline__ float ex2(float x) {
    float r;
    asm("ex2.approx.f32 %0, %1;" : "=f"(r) : "f"(x));
    return r;
}

// ---------------------------------------------------------------------------
// Kernel 1: Q projection, split-k x8 (unchanged champion).
// ---------------------------------------------------------------------------
__global__ __launch_bounds__(QDIM) void qproj_kernel(
    const float* __restrict__ z, const float* __restrict__ Wq,
    const float* __restrict__ bq)
{
    __shared__ float sz[MTOK * 24];
    const int b = blockIdx.x, kq = blockIdx.y, col = threadIdx.x;
    if (col < MTOK * 24) {
        const int m = col / 24, k = col - m * 24;
        sz[col] = z[b * MTOK * DMODEL + m * DMODEL + kq * 24 + k];
    }
    __syncthreads();

    float acc[MTOK];
    const float b0 = (kq == 0) ? bq[col] : 0.f;
    #pragma unroll
    for (int m = 0; m < MTOK; ++m) acc[m] = b0;

    const float* Wqp = Wq + (size_t)(kq * 24) * QDIM + col;
    #pragma unroll
    for (int k = 0; k < 24; ++k) {
        const float w = __ldg(Wqp + k * QDIM);
        #pragma unroll
        for (int m = 0; m < MTOK; ++m)
            acc[m] = fmaf(sz[m * 24 + k], w, acc[m]);
    }
    const int h = col / CH, c = col - h * CH;
    #pragma unroll
    for (int m = 0; m < MTOK; ++m)
        g_Qp[kq * (BATCH * RQ * CH) + (b * RQ + h * MTOK + m) * CH + c] = acc[m] * SCALE_F;
}

// ---------------------------------------------------------------------------
// Kernel 2: unpadded-GEMM fixed-max flash attention. 8 warps, occ 2.
// QK^T: S^T[128 n][24 q]: A = X^T (trans ldm, A-order map), B = Q (hoisted).
// PV^T: O^T[96 c][24 q]:  warps 0-5 own one 16-channel tile; B = P[q][n].
// 288 mma/tile/CTA, zero padding.
// ---------------------------------------------------------------------------
__global__ __launch_bounds__(256, 2) void attn_partial_kernel(const float* __restrict__ x)
{
    extern __shared__ char smem[];
    float*         sXf = (float*)(smem + OFF_XF);
    __nv_bfloat16* sQ  = (__nv_bfloat16*)(smem + OFF_Q);
    __nv_bfloat16* sX  = (__nv_bfloat16*)(smem + OFF_X);
    __nv_bfloat16* sP  = (__nv_bfloat16*)(smem + OFF_P);
    float*         sLr = (float*)(smem + OFF_LR);

    const int b = blockIdx.y, s = blockIdx.x;
    const int tid = threadIdx.x, lane = tid & 31, warp = tid >> 5;
    const int g = lane >> 2, tig = lane & 3;
    const int grp = lane >> 3;

    const uint32_t uQ  = smem_u32(sQ);
    const uint32_t uX  = smem_u32(sX);
    const uint32_t uP  = smem_u32(sP);
    const uint32_t uXf = smem_u32(sXf);

    const float* xb = x + (size_t)b * CH * HW + (size_t)s * CHUNK;

    // ---- cp.async tile 0 ----
    #pragma unroll
    for (int r = 0; r < 12; ++r) {
        const int i = tid + 256 * r;
        const int c = i >> 5, n4 = (i & 31) << 2;
        cpasync16(uXf + (c * FSTR + n4) * 4, xb + (size_t)c * HW + n4);
    }
    CP_COMMIT();

    // ---- stage Q (sum KQ split-k partials -> bf16), exactly 24 rows ----
    for (int i = tid; i < RQ * CH; i += 256) {
        const int r = i / CH, c = i - r * CH;
        const int idx = (b * RQ + r) * CH + c;
        float v = 0.f;
        #pragma unroll
        for (int k = 0; k < KQ; ++k) v += g_Qp[k * (BATCH * RQ * CH) + idx];
        sQ[r * QSTR + c] = __float2bfloat16(v);
    }
    __syncthreads();

    // ---- hoist Q B-fragments (loop-invariant): 18 x ldm_x2 = 36 regs ----
    uint32_t qb[6][3][2];
    #pragma unroll
    for (int ck = 0; ck < 6; ++ck)
        #pragma unroll
        for (int nt = 0; nt < 3; ++nt) {
            const int row = 8 * nt + (lane & 7);
            const int col = ck * 16 + ((lane >> 3) & 1) * 8;
            ldm_x2(qb[ck][nt][0], qb[ck][nt][1], uQ + (row * QSTR + col) * 2);
        }

    float runL[3][2];
    #pragma unroll
    for (int nt = 0; nt < 3; ++nt) { runL[nt][0] = 0.f; runL[nt][1] = 0.f; }
    float oacc[3][4];
    #pragma unroll
    for (int nt = 0; nt < 3; ++nt)
        #pragma unroll
        for (int e = 0; e < 4; ++e) oacc[nt][e] = 0.f;

    const int cw    = 16 * warp;                 // warp's 16 spatial cols (QK)
    const int ct    = warp;                      // PV channel tile (warps 0-5)
    const int row16 = (lane & 7) + 8 * (lane >> 4);
    const int q4    = (lane >> 3) & 1;

    for (int t = 0; t < TILES_PER; ++t) {
        CP_WAIT0();
        __syncthreads();   // staging t landed; PV(t-1) done with sX/sP

        // ---- convert OWN 16 spatial cols fp32 -> bf16 (R7 lane map) ----
        #pragma unroll
        for (int rr = 0; rr < 12; ++rr) {
            const int row = 16 * (rr >> 1) + row16;
            const int co  = cw + 8 * (rr & 1) + 4 * q4;
            float4 v = *reinterpret_cast<const float4*>(&sXf[row * FSTR + co]);
            uint2 pk2;
            pk2.x = pack_bf16(v.x, v.y);
            pk2.y = pack_bf16(v.z, v.w);
            *reinterpret_cast<uint2*>(&sX[row * XSTR + co]) = pk2;
        }
        __syncwarp();      // own-warp STS -> ldmatrix ordering

        // ---- QK^T on own 16 spatial rows: sc[nt][4], n = q (24, exact) ----
        float sc[3][4];
        #pragma unroll
        for (int nt = 0; nt < 3; ++nt)
            #pragma unroll
            for (int e = 0; e < 4; ++e) sc[nt][e] = 0.f;

        #pragma unroll
        for (int ck = 0; ck < 6; ++ck) {
            uint32_t a[4];
            // A = X^T m16k16 via trans ldm — A-fragment block order
            // {m0k0, m8k0, m0k8, m8k8}: k-row selected by grp>>1, m-col by grp&1
            // (exact R10-passing map; R15 had these two swapped = the bug)
            const int row = ck * 16 + (grp >> 1) * 8 + (lane & 7);  // channel (k)
            const int col = cw + (grp & 1) * 8;                     // spatial (m)
            ldm_x4_t(a[0], a[1], a[2], a[3], uX + (row * XSTR + col) * 2);
            #pragma unroll
            for (int nt = 0; nt < 3; ++nt)
                mma16816(sc[nt], a, qb[ck][nt][0], qb[ck][nt][1]);
        }

        // ---- P = 2^score (fixed max), private L, P -> sP[q][n] ----
        #pragma unroll
        for (int nt = 0; nt < 3; ++nt)
            #pragma unroll
            for (int hl = 0; hl < 2; ++hl) {
                const int n = cw + g + 8 * hl;                      // spatial
                #pragma unroll
                for (int j = 0; j < 2; ++j) {
                    const float p = ex2(sc[nt][hl * 2 + j]);
                    runL[nt][j] += p;
                    const int q = 8 * nt + 2 * tig + j;
                    sP[q * PSTR + n] = __float2bfloat16(p);
                }
            }
        __syncthreads();   // full sX + sP visible; sXf consumed

        // ---- prefetch tile t+1 (overlaps PV) ----
        if (t + 1 < TILES_PER) {
            const float* xt = xb + (t + 1) * TILE;
            #pragma unroll
            for (int r = 0; r < 12; ++r) {
                const int i = tid + 256 * r;
                const int c = i >> 5, n4 = (i & 31) << 2;
                cpasync16(uXf + (c * FSTR + n4) * 4, xt + (size_t)c * HW + n4);
            }
        }
        CP_COMMIT();

        // ---- PV^T: warps 0-5, own channel tile ct, k = 128 spatial ----
        if (warp < 6) {
            #pragma unroll
            for (int kc = 0; kc < 8; ++kc) {
                uint32_t a[4];
                // A = X m16k16 (canonical A map, R7-verified): rows = channels
                const int row = ct * 16 + (lane & 15);
                const int col = kc * 16 + (lane >> 4) * 8;
                ldm_x4(a[0], a[1], a[2], a[3], uX + (row * XSTR + col) * 2);
                #pragma unroll
                for (int nt = 0; nt < 3; ++nt) {
                    uint32_t b0, b1;
                    const int rq = 8 * nt + (lane & 7);
                    const int ck = kc * 16 + ((lane >> 3) & 1) * 8;
                    ldm_x2(b0, b1, uP + (rq * PSTR + ck) * 2);
                    mma16816(oacc[nt], a, b0, b1);
                }
            }
        }
    }

    // ---- epilogue: O^T fragments scatter directly to g_Ox ----
    const int base = (b * SPLITS + s) * RQ;
    if (warp < 6) {
        #pragma unroll
        for (int nt = 0; nt < 3; ++nt)
            #pragma unroll
            for (int hl = 0; hl < 2; ++hl)
                #pragma unroll
                for (int j = 0; j < 2; ++j) {
                    const int q = 8 * nt + 2 * tig + j;
                    const int c = ct * 16 + g + 8 * hl;
                    g_Ox[(base + q) * CH + c] = oacc[nt][hl * 2 + j];
                }
    }
    // L: reduce over g lanes (offsets 4,8,16), then cross-warp
    #pragma unroll
    for (int nt = 0; nt < 3; ++nt)
        #pragma unroll
        for (int j = 0; j < 2; ++j) {
            runL[nt][j] += __shfl_xor_sync(0xffffffffu, runL[nt][j], 4);
            runL[nt][j] += __shfl_xor_sync(0xffffffffu, runL[nt][j], 8);
            runL[nt][j] += __shfl_xor_sync(0xffffffffu, runL[nt][j], 16);
        }
    if (lane < 4) {
        #pragma unroll
        for (int nt = 0; nt < 3; ++nt) {
            sLr[warp * 32 + 8 * nt + 2 * lane]     = runL[nt][0];
            sLr[warp * 32 + 8 * nt + 2 * lane + 1] = runL[nt][1];
        }
    }
    __syncthreads();
    if (tid < RQ) {
        float L = 0.f;
        #pragma unroll
        for (int w = 0; w < 8; ++w) L += sLr[w * 32 + tid];
        g_Lx[base + tid] = L;
    }
}

// ---------------------------------------------------------------------------
// Kernel 3: combine split partials + output projection + residual (unchanged).
// ---------------------------------------------------------------------------
__global__ __launch_bounds__(DMODEL) void combine_proj_kernel(
    const float* __restrict__ z, const float* __restrict__ Wo,
    const float* __restrict__ bo, float* __restrict__ out)
{
    __shared__ float sOf[RQ * CH];
    __shared__ float sLi[RQ];
    const int b = blockIdx.x, tid = threadIdx.x;

    if (tid < RQ) {
        float L = 0.f;
        #pragma unroll
        for (int s = 0; s < SPLITS; ++s)
            L += g_Lx[(b * SPLITS + s) * RQ + tid];
        sLi[tid] = 1.f / L;
    }
    __syncthreads();

    for (int o = tid; o < RQ * CH; o += DMODEL) {
        const int q = o / CH, c = o - q * CH;
        float a = 0.f;
        #pragma unroll
        for (int s = 0; s < SPLITS; ++s)
            a += g_Ox[((b * SPLITS + s) * RQ + q) * CH + c];
        sOf[o] = a * sLi[q];
    }
    __syncthreads();

    float accv[MTOK];
    #pragma unroll
    for (int m = 0; m < MTOK; ++m)
        accv[m] = z[(b * MTOK + m) * DMODEL + tid] + bo[tid];

    for (int h = 0; h < HEADS; ++h) {
        #pragma unroll 4
        for (int c = 0; c < CH; ++c) {
            const float w = Wo[(h * CH + c) * DMODEL + tid];
            #pragma unroll
            for (int m = 0; m < MTOK; ++m)
                accv[m] = fmaf(sOf[(h * MTOK + m) * CH + c], w, accv[m]);
        }
    }
    #pragma unroll
    for (int m = 0; m < MTOK; ++m)
        out[(b * MTOK + m) * DMODEL + tid] = accv[m];
}

// ---------------------------------------------------------------------------
extern "C" void kernel_launch(void* const* d_in, const int* in_sizes, int n_in,
                              void* d_out, int out_size)
{
    const float* x  = (const float*)d_in[0];
    const float* z  = (const float*)d_in[1];
    const float* Wq = (const float*)d_in[2];
    const float* bq = (const float*)d_in[3];
    const float* Wo = (const float*)d_in[4];
    const float* bo = (const float*)d_in[5];
    float* out = (float*)d_out;

    cudaFuncSetAttribute(attn_partial_kernel,
                         cudaFuncAttributeMaxDynamicSharedMemorySize, SMEM_TOT);

    qproj_kernel<<<dim3(BATCH, KQ), QDIM>>>(z, Wq, bq);
    attn_partial_kernel<<<dim3(SPLITS, BATCH), 256, SMEM_TOT>>>(x);
    combine_proj_kernel<<<BATCH, DMODEL>>>(z, Wo, bo, out);
}